// round 13
// baseline (speedup 1.0000x reference)
#include <cuda_runtime.h>
#include <cuda_bf16.h>
#include <cstdint>

#define NROWS 1048576
#define DIM   128
#define NSEG  4096

// Scratch (__device__ globals per allocation-free rule)
__device__ float g_xs[NSEG * DIM];                          // segment sums (2 MB)
__device__ float g_xm[NSEG * DIM];                          // xs @ Lambda^T (2 MB)
__device__ __align__(16) __nv_bfloat16 g_GbI[DIM * 136];    // Gamma bf16, padded-row image

#define ASTRIDE 136                         // halves per smem row (pad 8)
#define K3_SMEM (2 * 128 * ASTRIDE * 2)     // 69632 bytes

__device__ __forceinline__ uint32_t smem_u32(const void* p) {
    uint32_t a;
    asm("{ .reg .u64 t; cvta.to.shared.u64 t, %1; cvt.u32.u64 %0, t; }" : "=r"(a) : "l"(p));
    return a;
}
__device__ __forceinline__ uint32_t pack_bf16x2(float lo, float hi) {
    uint32_t r;
    asm("cvt.rn.bf16x2.f32 %0, %1, %2;" : "=r"(r) : "f"(hi), "f"(lo));
    return r;
}
__device__ __forceinline__ float4 ldcs_f4(const float* p) {
    float4 v;
    asm volatile("ld.global.cs.v4.f32 {%0,%1,%2,%3}, [%4];"
                 : "=f"(v.x), "=f"(v.y), "=f"(v.z), "=f"(v.w) : "l"(p));
    return v;
}
__device__ __forceinline__ void stcs_f2(float* p, float2 v) {
    asm volatile("st.global.cs.v2.f32 [%0], {%1,%2};" :: "l"(p), "f"(v.x), "f"(v.y) : "memory");
}

// ---------------------------------------------------------------------------
// Kernel 0: zero g_xs, build padded-row bf16 image of Gamma [n][k]
// ---------------------------------------------------------------------------
__global__ void k0_init(const float* __restrict__ GW) {
    int idx = blockIdx.x * blockDim.x + threadIdx.x;
    if (idx < NSEG * DIM) g_xs[idx] = 0.0f;
    if (idx < DIM * DIM) {
        int n = idx >> 7, k = idx & 127;
        g_GbI[n * ASTRIDE + k] = __float2bfloat16(GW[idx]);
    }
}

// ---------------------------------------------------------------------------
// Kernel 1: segment sum (sorted ids). Explicit 8-wide load batching + .cs.
// ---------------------------------------------------------------------------
__global__ __launch_bounds__(256) void k1_segsum(const float* __restrict__ x,
                                                 const int* __restrict__ seg) {
    int t = threadIdx.x;
    int stream = t >> 5;
    int c = (t & 31) * 4;
    int base = blockIdx.x * 1024 + stream;

    float4 acc = make_float4(0.f, 0.f, 0.f, 0.f);
    int cur = seg[base];

    for (int ii = 0; ii < 16; ii++) {
        int s8[8];
        float4 v8[8];
        #pragma unroll
        for (int j = 0; j < 8; j++) {
            int r = base + (ii * 8 + j) * 8;
            s8[j] = seg[r];
            v8[j] = ldcs_f4(x + (size_t)r * DIM + c);
        }
        #pragma unroll
        for (int j = 0; j < 8; j++) {
            if (s8[j] != cur) {
                float* d = g_xs + (size_t)cur * DIM + c;
                atomicAdd(d + 0, acc.x); atomicAdd(d + 1, acc.y);
                atomicAdd(d + 2, acc.z); atomicAdd(d + 3, acc.w);
                acc = make_float4(0.f, 0.f, 0.f, 0.f);
                cur = s8[j];
            }
            acc.x += v8[j].x; acc.y += v8[j].y;
            acc.z += v8[j].z; acc.w += v8[j].w;
        }
    }
    float* d = g_xs + (size_t)cur * DIM + c;
    atomicAdd(d + 0, acc.x); atomicAdd(d + 1, acc.y);
    atomicAdd(d + 2, acc.z); atomicAdd(d + 3, acc.w);
}

// ---------------------------------------------------------------------------
// Kernel 2: g_xm = g_xs @ Lambda_W^T (fp32 exact)
// ---------------------------------------------------------------------------
__global__ __launch_bounds__(128) void k2_xm(const float* __restrict__ LW) {
    extern __shared__ float sm2[];
    float* Lt  = sm2;                 // [128][129]
    float* xss = sm2 + 128 * 129;     // [16][128]
    int t = threadIdx.x;
    int R0 = blockIdx.x * 16;

    for (int i = 0; i < 128; i++) {
        int e = i * 128 + t;
        int j = e >> 7, k = e & 127;
        Lt[k * 129 + j] = LW[e];
    }
    for (int i = 0; i < 16; i++) {
        int e = i * 128 + t;
        int r = e >> 7, k = e & 127;
        xss[r * 128 + k] = g_xs[(size_t)(R0 + r) * DIM + k];
    }
    __syncthreads();

    float acc[16];
    #pragma unroll
    for (int r = 0; r < 16; r++) acc[r] = 0.f;
    for (int k = 0; k < 128; k++) {
        float lv = Lt[k * 129 + t];
        #pragma unroll
        for (int r = 0; r < 16; r++) acc[r] += xss[r * 128 + k] * lv;
    }
    #pragma unroll
    for (int r = 0; r < 16; r++)
        g_xm[(size_t)(R0 + r) * DIM + t] = acc[r];
}

// ---------------------------------------------------------------------------
// Kernel 3: out = x @ Gamma^T (bf16 HMMA) + bias - xm[seg]
// Warp tile 16x128 (a-frags fully preloaded = 32 regs). n-pair-outermost loop
// with INTERLEAVED epilogue: each 16-col slice is stored right after its MMAs
// -> store stream spread across the whole mainloop (overlaps reads).
// Low live-reg count -> __launch_bounds__(256,3): 3 CTAs/SM, 24 warps.
// ---------------------------------------------------------------------------
__global__ __launch_bounds__(256, 3) void k3_main(const float* __restrict__ x,
                                                  const int* __restrict__ seg,
                                                  const float* __restrict__ bias,
                                                  float* __restrict__ out) {
    extern __shared__ __nv_bfloat16 sm3[];
    __nv_bfloat16* As = sm3;                       // [128][136]
    __nv_bfloat16* Bs = sm3 + 128 * ASTRIDE;       // [128][136]  Bs[n][k]

    int tid  = threadIdx.x;
    int warp = tid >> 5;
    int lane = tid & 31;
    int r0 = blockIdx.x * 128;
    int m0 = warp * 16;
    uint32_t sbB = smem_u32(Bs);
    uint32_t sbA = smem_u32(As);

    // Stage B via flat cp.async of padded image (34816 B)
    #pragma unroll
    for (int i = 0; i < 9; i++) {
        int e = i * 256 + tid;
        if (e < (128 * ASTRIDE * 2) / 16)
            asm volatile("cp.async.cg.shared.global [%0], [%1], 16;"
                         :: "r"(sbB + e * 16),
                            "l"((const char*)g_GbI + e * 16) : "memory");
    }
    asm volatile("cp.async.commit_group;" ::: "memory");

    // Stage A: LDG.cs fp32 -> bf16 -> STS.128
    #pragma unroll
    for (int i = 0; i < 8; i++) {
        int e = i * 256 + tid;
        int row = e >> 4, g2 = e & 15;
        const float* src = x + (size_t)(r0 + row) * DIM + g2 * 8;
        float4 v0 = ldcs_f4(src);
        float4 v1 = ldcs_f4(src + 4);
        uint32_t p0 = pack_bf16x2(v0.x, v0.y);
        uint32_t p1 = pack_bf16x2(v0.z, v0.w);
        uint32_t p2 = pack_bf16x2(v1.x, v1.y);
        uint32_t p3 = pack_bf16x2(v1.z, v1.w);
        asm volatile("st.shared.v4.b32 [%0], {%1,%2,%3,%4};"
                     :: "r"(sbA + (row * ASTRIDE + g2 * 8) * 2),
                        "r"(p0), "r"(p1), "r"(p2), "r"(p3) : "memory");
    }

    // Epilogue row ownership (one seg lookup pair per lane)
    int g  = lane >> 2;
    int t4 = lane & 3;
    int ra = r0 + m0 + g;
    int rb = ra + 8;
    int sa = seg[ra];
    int sb = seg[rb];

    asm volatile("cp.async.wait_group 0;" ::: "memory");
    __syncthreads();

    // Preload ALL a-fragments (8 ks x 4 regs = 32 regs)
    uint32_t a[8][4];
    {
        uint32_t ap = sbA + ((m0 + (lane & 15)) * ASTRIDE + ((lane >> 4) << 3)) * 2;
        #pragma unroll
        for (int ks = 0; ks < 8; ks++) {
            asm volatile(
                "ldmatrix.sync.aligned.m8n8.x4.shared.b16 {%0,%1,%2,%3}, [%4];"
                : "=r"(a[ks][0]), "=r"(a[ks][1]), "=r"(a[ks][2]), "=r"(a[ks][3])
                : "r"(ap + ks * 32));
        }
    }

    uint32_t boff = sbB + (((lane & 7) + ((lane >> 4) << 3)) * ASTRIDE
                           + (((lane >> 3) & 1) << 3)) * 2;
    const float* xa = g_xm + (size_t)sa * DIM;
    const float* xb = g_xm + (size_t)sb * DIM;
    float* outa = out + (size_t)ra * DIM;
    float* outb = out + (size_t)rb * DIM;

    // n-pair-outermost: compute 16 cols, then store them immediately
    #pragma unroll
    for (int ntp = 0; ntp < 8; ntp++) {
        float acc0[4] = {0.f, 0.f, 0.f, 0.f};
        float acc1[4] = {0.f, 0.f, 0.f, 0.f};
        uint32_t bbase = boff + (ntp * 16 * ASTRIDE) * 2;
        #pragma unroll
        for (int ks = 0; ks < 8; ks++) {
            uint32_t b0, b1, b2, b3;
            asm volatile(
                "ldmatrix.sync.aligned.m8n8.x4.shared.b16 {%0,%1,%2,%3}, [%4];"
                : "=r"(b0), "=r"(b1), "=r"(b2), "=r"(b3)
                : "r"(bbase + ks * 32));
            asm volatile(
                "mma.sync.aligned.m16n8k16.row.col.f32.bf16.bf16.f32 "
                "{%0,%1,%2,%3}, {%4,%5,%6,%7}, {%8,%9}, {%0,%1,%2,%3};\n"
                : "+f"(acc0[0]), "+f"(acc0[1]), "+f"(acc0[2]), "+f"(acc0[3])
                : "r"(a[ks][0]), "r"(a[ks][1]), "r"(a[ks][2]), "r"(a[ks][3]),
                  "r"(b0), "r"(b1));
            asm volatile(
                "mma.sync.aligned.m16n8k16.row.col.f32.bf16.bf16.f32 "
                "{%0,%1,%2,%3}, {%4,%5,%6,%7}, {%8,%9}, {%0,%1,%2,%3};\n"
                : "+f"(acc1[0]), "+f"(acc1[1]), "+f"(acc1[2]), "+f"(acc1[3])
                : "r"(a[ks][0]), "r"(a[ks][1]), "r"(a[ks][2]), "r"(a[ks][3]),
                  "r"(b2), "r"(b3));
        }

        // Immediate epilogue for these 16 columns
        int j0 = ntp * 16 + 2 * t4;
        int j1 = j0 + 8;
        float2 bv0 = *(const float2*)(bias + j0);
        float2 bv1 = *(const float2*)(bias + j1);
        float2 ma0 = *(const float2*)(xa + j0);
        float2 ma1 = *(const float2*)(xa + j1);
        float2 mb0 = *(const float2*)(xb + j0);
        float2 mb1 = *(const float2*)(xb + j1);
        float2 o;
        o.x = acc0[0] + bv0.x - ma0.x;  o.y = acc0[1] + bv0.y - ma0.y;
        stcs_f2(outa + j0, o);
        o.x = acc0[2] + bv0.x - mb0.x;  o.y = acc0[3] + bv0.y - mb0.y;
        stcs_f2(outb + j0, o);
        o.x = acc1[0] + bv1.x - ma1.x;  o.y = acc1[1] + bv1.y - ma1.y;
        stcs_f2(outa + j1, o);
        o.x = acc1[2] + bv1.x - mb1.x;  o.y = acc1[3] + bv1.y - mb1.y;
        stcs_f2(outb + j1, o);
    }
}

// ---------------------------------------------------------------------------
extern "C" void kernel_launch(void* const* d_in, const int* in_sizes, int n_in,
                              void* d_out, int out_size) {
    const float* x   = (const float*)d_in[0];
    const int*   seg = (const int*)d_in[1];
    const float* GW = nullptr;
    const float* Gb = nullptr;
    const float* LW = nullptr;
    for (int i = 2; i < n_in; i++) {
        int s = in_sizes[i];
        if (s == DIM * DIM) { if (!GW) GW = (const float*)d_in[i]; else LW = (const float*)d_in[i]; }
        else if (s == DIM) { Gb = (const float*)d_in[i]; }
    }
    float* out = (float*)d_out;

    cudaFuncSetAttribute(k2_xm,   cudaFuncAttributeMaxDynamicSharedMemorySize, 74240);
    cudaFuncSetAttribute(k3_main, cudaFuncAttributeMaxDynamicSharedMemorySize, K3_SMEM);

    k0_init<<<2048, 256>>>(GW);
    k1_segsum<<<NROWS / 1024, 256>>>(x, seg);
    k2_xm<<<NSEG / 16, 128, 74240>>>(LW);
    k3_main<<<NROWS / 128, 256, K3_SMEM>>>(x, seg, Gb, out);
}

// round 14
// speedup vs baseline: 1.1410x; 1.1410x over previous
#include <cuda_runtime.h>
#include <cuda_bf16.h>
#include <cstdint>

#define NROWS 1048576
#define DIM   128
#define NSEG  4096

// Scratch (__device__ globals per allocation-free rule)
__device__ float g_xs[NSEG * DIM];                          // segment sums (2 MB)
__device__ float g_xm[NSEG * DIM];                          // xs @ Lambda^T (2 MB)
__device__ __align__(16) __nv_bfloat16 g_GbI[DIM * 136];    // Gamma bf16, padded-row image

#define ASTRIDE 136                         // halves per smem row (pad 8)
#define K3_SMEM (2 * 128 * ASTRIDE * 2)     // 69632 bytes (B + A)
#define TILES_PER_CTA 4

__device__ __forceinline__ uint32_t smem_u32(const void* p) {
    uint32_t a;
    asm("{ .reg .u64 t; cvta.to.shared.u64 t, %1; cvt.u32.u64 %0, t; }" : "=r"(a) : "l"(p));
    return a;
}
__device__ __forceinline__ uint32_t pack_bf16x2(float lo, float hi) {
    uint32_t r;
    asm("cvt.rn.bf16x2.f32 %0, %1, %2;" : "=r"(r) : "f"(hi), "f"(lo));
    return r;
}
__device__ __forceinline__ float4 ldcs_f4(const float* p) {
    float4 v;
    asm volatile("ld.global.cs.v4.f32 {%0,%1,%2,%3}, [%4];"
                 : "=f"(v.x), "=f"(v.y), "=f"(v.z), "=f"(v.w) : "l"(p));
    return v;
}
__device__ __forceinline__ void stcs_f2(float* p, float2 v) {
    asm volatile("st.global.cs.v2.f32 [%0], {%1,%2};" :: "l"(p), "f"(v.x), "f"(v.y) : "memory");
}

// ---------------------------------------------------------------------------
// Kernel 0: zero g_xs, build padded-row bf16 image of Gamma [n][k]
// ---------------------------------------------------------------------------
__global__ void k0_init(const float* __restrict__ GW) {
    int idx = blockIdx.x * blockDim.x + threadIdx.x;
    if (idx < NSEG * DIM) g_xs[idx] = 0.0f;
    if (idx < DIM * DIM) {
        int n = idx >> 7, k = idx & 127;
        g_GbI[n * ASTRIDE + k] = __float2bfloat16(GW[idx]);
    }
}

// ---------------------------------------------------------------------------
// Kernel 1: segment sum (sorted ids). Explicit 8-wide load batching + .cs.
// ---------------------------------------------------------------------------
__global__ __launch_bounds__(256) void k1_segsum(const float* __restrict__ x,
                                                 const int* __restrict__ seg) {
    int t = threadIdx.x;
    int stream = t >> 5;
    int c = (t & 31) * 4;
    int base = blockIdx.x * 1024 + stream;

    float4 acc = make_float4(0.f, 0.f, 0.f, 0.f);
    int cur = seg[base];

    for (int ii = 0; ii < 16; ii++) {
        int s8[8];
        float4 v8[8];
        #pragma unroll
        for (int j = 0; j < 8; j++) {
            int r = base + (ii * 8 + j) * 8;
            s8[j] = seg[r];
            v8[j] = ldcs_f4(x + (size_t)r * DIM + c);
        }
        #pragma unroll
        for (int j = 0; j < 8; j++) {
            if (s8[j] != cur) {
                float* d = g_xs + (size_t)cur * DIM + c;
                atomicAdd(d + 0, acc.x); atomicAdd(d + 1, acc.y);
                atomicAdd(d + 2, acc.z); atomicAdd(d + 3, acc.w);
                acc = make_float4(0.f, 0.f, 0.f, 0.f);
                cur = s8[j];
            }
            acc.x += v8[j].x; acc.y += v8[j].y;
            acc.z += v8[j].z; acc.w += v8[j].w;
        }
    }
    float* d = g_xs + (size_t)cur * DIM + c;
    atomicAdd(d + 0, acc.x); atomicAdd(d + 1, acc.y);
    atomicAdd(d + 2, acc.z); atomicAdd(d + 3, acc.w);
}

// ---------------------------------------------------------------------------
// Kernel 2: g_xm = g_xs @ Lambda_W^T (fp32 exact)
// ---------------------------------------------------------------------------
__global__ __launch_bounds__(128) void k2_xm(const float* __restrict__ LW) {
    extern __shared__ float sm2[];
    float* Lt  = sm2;                 // [128][129]
    float* xss = sm2 + 128 * 129;     // [16][128]
    int t = threadIdx.x;
    int R0 = blockIdx.x * 16;

    for (int i = 0; i < 128; i++) {
        int e = i * 128 + t;
        int j = e >> 7, k = e & 127;
        Lt[k * 129 + j] = LW[e];
    }
    for (int i = 0; i < 16; i++) {
        int e = i * 128 + t;
        int r = e >> 7, k = e & 127;
        xss[r * 128 + k] = g_xs[(size_t)(R0 + r) * DIM + k];
    }
    __syncthreads();

    float acc[16];
    #pragma unroll
    for (int r = 0; r < 16; r++) acc[r] = 0.f;
    for (int k = 0; k < 128; k++) {
        float lv = Lt[k * 129 + t];
        #pragma unroll
        for (int r = 0; r < 16; r++) acc[r] += xss[r * 128 + k] * lv;
    }
    #pragma unroll
    for (int r = 0; r < 16; r++)
        g_xm[(size_t)(R0 + r) * DIM + t] = acc[r];
}

// ---------------------------------------------------------------------------
// Kernel 3: out = x @ Gamma^T (bf16 HMMA) + bias - xm[seg]
// FREE-RUNNING WARPS: warp tile 16x128 -> A is warp-private, so NO block
// barriers after the one-time B stage. Each warp stages its own 16 rows
// (LDG.cs -> cvt -> STS, __syncwarp), builds fragments, MMAs with the
// R12-interleaved epilogue (stores spread through the n-loop). T=4 tiles
// per CTA so warps desynchronize and the SM mixes read/MMA/store streams.
// ---------------------------------------------------------------------------
__global__ __launch_bounds__(256, 2) void k3_main(const float* __restrict__ x,
                                                  const int* __restrict__ seg,
                                                  const float* __restrict__ bias,
                                                  float* __restrict__ out) {
    extern __shared__ __nv_bfloat16 sm3[];
    __nv_bfloat16* Bs = sm3;                       // [128][136]  Bs[n][k]
    __nv_bfloat16* As = sm3 + 128 * ASTRIDE;       // [128][136]  warp-private slices

    int tid  = threadIdx.x;
    int warp = tid >> 5;
    int lane = tid & 31;
    int m0 = warp * 16;
    uint32_t sbB = smem_u32(Bs);
    uint32_t sbA = smem_u32(As);

    // One-time B stage via flat cp.async of padded image (34816 B)
    #pragma unroll
    for (int i = 0; i < 9; i++) {
        int e = i * 256 + tid;
        if (e < (128 * ASTRIDE * 2) / 16)
            asm volatile("cp.async.cg.shared.global [%0], [%1], 16;"
                         :: "r"(sbB + e * 16),
                            "l"((const char*)g_GbI + e * 16) : "memory");
    }
    asm volatile("cp.async.commit_group;" ::: "memory");
    asm volatile("cp.async.wait_group 0;" ::: "memory");
    __syncthreads();        // the ONLY block barrier

    int g  = lane >> 2;
    int t4 = lane & 3;

    // Loop-invariant bias regs and fragment offsets
    float2 bias_r[8][2];
    #pragma unroll
    for (int ntp = 0; ntp < 8; ntp++) {
        bias_r[ntp][0] = *(const float2*)(bias + ntp * 16 + 2 * t4);
        bias_r[ntp][1] = *(const float2*)(bias + ntp * 16 + 2 * t4 + 8);
    }
    uint32_t ap = sbA + ((m0 + (lane & 15)) * ASTRIDE + ((lane >> 4) << 3)) * 2;
    uint32_t boff = sbB + (((lane & 7) + ((lane >> 4) << 3)) * ASTRIDE
                           + (((lane >> 3) & 1) << 3)) * 2;
    uint32_t sts_base = sbA + (m0 * ASTRIDE + lane * 4) * 2;

    #pragma unroll 1
    for (int t = 0; t < TILES_PER_CTA; t++) {
        int r0 = (blockIdx.x * TILES_PER_CTA + t) * 128;

        // Stage own 16 rows: LDG.128 (.cs) -> bf16 -> STS.64, warp-private
        const float* xrow = x + (size_t)(r0 + m0) * DIM + lane * 4;
        #pragma unroll
        for (int r = 0; r < 16; r += 4) {
            float4 v0 = ldcs_f4(xrow + (size_t)(r + 0) * DIM);
            float4 v1 = ldcs_f4(xrow + (size_t)(r + 1) * DIM);
            float4 v2 = ldcs_f4(xrow + (size_t)(r + 2) * DIM);
            float4 v3 = ldcs_f4(xrow + (size_t)(r + 3) * DIM);
            uint2 p0 = make_uint2(pack_bf16x2(v0.x, v0.y), pack_bf16x2(v0.z, v0.w));
            uint2 p1 = make_uint2(pack_bf16x2(v1.x, v1.y), pack_bf16x2(v1.z, v1.w));
            uint2 p2 = make_uint2(pack_bf16x2(v2.x, v2.y), pack_bf16x2(v2.z, v2.w));
            uint2 p3 = make_uint2(pack_bf16x2(v3.x, v3.y), pack_bf16x2(v3.z, v3.w));
            asm volatile("st.shared.v2.b32 [%0], {%1,%2};"
                         :: "r"(sts_base + (r + 0) * ASTRIDE * 2), "r"(p0.x), "r"(p0.y) : "memory");
            asm volatile("st.shared.v2.b32 [%0], {%1,%2};"
                         :: "r"(sts_base + (r + 1) * ASTRIDE * 2), "r"(p1.x), "r"(p1.y) : "memory");
            asm volatile("st.shared.v2.b32 [%0], {%1,%2};"
                         :: "r"(sts_base + (r + 2) * ASTRIDE * 2), "r"(p2.x), "r"(p2.y) : "memory");
            asm volatile("st.shared.v2.b32 [%0], {%1,%2};"
                         :: "r"(sts_base + (r + 3) * ASTRIDE * 2), "r"(p3.x), "r"(p3.y) : "memory");
        }
        __syncwarp();

        // Epilogue row ownership
        int ra = r0 + m0 + g;
        int rb = ra + 8;
        int sa = seg[ra];
        int sb = seg[rb];
        const float* xa = g_xm + (size_t)sa * DIM;
        const float* xb = g_xm + (size_t)sb * DIM;
        float* outa = out + (size_t)ra * DIM;
        float* outb = out + (size_t)rb * DIM;

        // Preload a-fragments (8 ks x 4 regs)
        uint32_t a[8][4];
        #pragma unroll
        for (int ks = 0; ks < 8; ks++) {
            asm volatile(
                "ldmatrix.sync.aligned.m8n8.x4.shared.b16 {%0,%1,%2,%3}, [%4];"
                : "=r"(a[ks][0]), "=r"(a[ks][1]), "=r"(a[ks][2]), "=r"(a[ks][3])
                : "r"(ap + ks * 32));
        }

        // n-pair-outermost with interleaved epilogue stores
        #pragma unroll
        for (int ntp = 0; ntp < 8; ntp++) {
            float acc0[4] = {0.f, 0.f, 0.f, 0.f};
            float acc1[4] = {0.f, 0.f, 0.f, 0.f};
            uint32_t bbase = boff + (ntp * 16 * ASTRIDE) * 2;
            #pragma unroll
            for (int ks = 0; ks < 8; ks++) {
                uint32_t b0, b1, b2, b3;
                asm volatile(
                    "ldmatrix.sync.aligned.m8n8.x4.shared.b16 {%0,%1,%2,%3}, [%4];"
                    : "=r"(b0), "=r"(b1), "=r"(b2), "=r"(b3)
                    : "r"(bbase + ks * 32));
                asm volatile(
                    "mma.sync.aligned.m16n8k16.row.col.f32.bf16.bf16.f32 "
                    "{%0,%1,%2,%3}, {%4,%5,%6,%7}, {%8,%9}, {%0,%1,%2,%3};\n"
                    : "+f"(acc0[0]), "+f"(acc0[1]), "+f"(acc0[2]), "+f"(acc0[3])
                    : "r"(a[ks][0]), "r"(a[ks][1]), "r"(a[ks][2]), "r"(a[ks][3]),
                      "r"(b0), "r"(b1));
                asm volatile(
                    "mma.sync.aligned.m16n8k16.row.col.f32.bf16.bf16.f32 "
                    "{%0,%1,%2,%3}, {%4,%5,%6,%7}, {%8,%9}, {%0,%1,%2,%3};\n"
                    : "+f"(acc1[0]), "+f"(acc1[1]), "+f"(acc1[2]), "+f"(acc1[3])
                    : "r"(a[ks][0]), "r"(a[ks][1]), "r"(a[ks][2]), "r"(a[ks][3]),
                      "r"(b2), "r"(b3));
            }
            int j0 = ntp * 16 + 2 * t4;
            int j1 = j0 + 8;
            float2 ma0 = *(const float2*)(xa + j0);
            float2 ma1 = *(const float2*)(xa + j1);
            float2 mb0 = *(const float2*)(xb + j0);
            float2 mb1 = *(const float2*)(xb + j1);
            float2 o;
            o.x = acc0[0] + bias_r[ntp][0].x - ma0.x;
            o.y = acc0[1] + bias_r[ntp][0].y - ma0.y;
            stcs_f2(outa + j0, o);
            o.x = acc0[2] + bias_r[ntp][0].x - mb0.x;
            o.y = acc0[3] + bias_r[ntp][0].y - mb0.y;
            stcs_f2(outb + j0, o);
            o.x = acc1[0] + bias_r[ntp][1].x - ma1.x;
            o.y = acc1[1] + bias_r[ntp][1].y - ma1.y;
            stcs_f2(outa + j1, o);
            o.x = acc1[2] + bias_r[ntp][1].x - mb1.x;
            o.y = acc1[3] + bias_r[ntp][1].y - mb1.y;
            stcs_f2(outb + j1, o);
        }
    }
}

// ---------------------------------------------------------------------------
extern "C" void kernel_launch(void* const* d_in, const int* in_sizes, int n_in,
                              void* d_out, int out_size) {
    const float* x   = (const float*)d_in[0];
    const int*   seg = (const int*)d_in[1];
    const float* GW = nullptr;
    const float* Gb = nullptr;
    const float* LW = nullptr;
    for (int i = 2; i < n_in; i++) {
        int s = in_sizes[i];
        if (s == DIM * DIM) { if (!GW) GW = (const float*)d_in[i]; else LW = (const float*)d_in[i]; }
        else if (s == DIM) { Gb = (const float*)d_in[i]; }
    }
    float* out = (float*)d_out;

    cudaFuncSetAttribute(k2_xm,   cudaFuncAttributeMaxDynamicSharedMemorySize, 74240);
    cudaFuncSetAttribute(k3_main, cudaFuncAttributeMaxDynamicSharedMemorySize, K3_SMEM);

    k0_init<<<2048, 256>>>(GW);
    k1_segsum<<<NROWS / 1024, 256>>>(x, seg);
    k2_xm<<<NSEG / 16, 128, 74240>>>(LW);
    k3_main<<<NROWS / (128 * TILES_PER_CTA), 256, K3_SMEM>>>(x, seg, Gb, out);
}